// round 1
// baseline (speedup 1.0000x reference)
#include <cuda_runtime.h>
#include <cuda_bf16.h>

#define N_NODES 600000
#define N_EDGES 2400000
#define LEADS 12
#define NUM_GRAPHS 50000
#define F_IN 128
#define HDIM 64
#define OUT_DIM 32

// ---------------- scratch (device globals: no allocation allowed) -------------
__device__ float g_h[(size_t)N_NODES * HDIM];    // GEMM output h' = h @ W
__device__ float g_agg[(size_t)N_NODES * HDIM];  // aggregated / layer output
__device__ float g_dinv[N_NODES];
__device__ int   g_deg[N_NODES];

// ---------------- degree / normalization --------------------------------------
__global__ void k_deg_init() {
    int i = blockIdx.x * blockDim.x + threadIdx.x;
    if (i < N_NODES) g_deg[i] = 1;  // self loop
}

__global__ void k_deg_count(const int* __restrict__ dst) {
    int e = blockIdx.x * blockDim.x + threadIdx.x;
    if (e < N_EDGES) atomicAdd(&g_deg[dst[e]], 1);
}

__global__ void k_dinv() {
    int i = blockIdx.x * blockDim.x + threadIdx.x;
    if (i < N_NODES) g_dinv[i] = rsqrtf((float)g_deg[i]);
}

// ---------------- GEMM: C[N,64] = A[N,K] @ W[K,64] ----------------------------
// BM rows per block, 256 threads, thread tile TM x 4 (TM = BM/16).
template<int K, int BM, int TM>
__global__ void k_gemm64(const float* __restrict__ A, const float* __restrict__ W,
                         float* __restrict__ C) {
    __shared__ float sA[BM * K];
    __shared__ float sW[K * 64];
    int tid = threadIdx.x;
    size_t r0 = (size_t)blockIdx.x * BM;

    const float4* W4 = (const float4*)W;
    float4* sW4 = (float4*)sW;
    #pragma unroll
    for (int i = tid; i < K * 16; i += 256) sW4[i] = W4[i];

    const float4* A4 = (const float4*)(A + r0 * K);
    float4* sA4 = (float4*)sA;
    #pragma unroll
    for (int i = tid; i < BM * K / 4; i += 256) sA4[i] = A4[i];
    __syncthreads();

    int ci = tid & 15;         // column group: cols [4ci, 4ci+3]
    int ri = tid >> 4;         // row group:    rows [TM*ri, TM*ri+TM-1]
    float acc[TM][4];
    #pragma unroll
    for (int j = 0; j < TM; j++) { acc[j][0]=0.f; acc[j][1]=0.f; acc[j][2]=0.f; acc[j][3]=0.f; }

    #pragma unroll 16
    for (int k = 0; k < K; k++) {
        float4 w = sW4[k * 16 + ci];
        #pragma unroll
        for (int j = 0; j < TM; j++) {
            float a = sA[(ri * TM + j) * K + k];   // warp-broadcast
            acc[j][0] += a * w.x;
            acc[j][1] += a * w.y;
            acc[j][2] += a * w.z;
            acc[j][3] += a * w.w;
        }
    }

    float4* C4 = (float4*)(C + r0 * 64);
    #pragma unroll
    for (int j = 0; j < TM; j++)
        C4[(ri * TM + j) * 16 + ci] = make_float4(acc[j][0], acc[j][1], acc[j][2], acc[j][3]);
}

// ---------------- self-loop init: agg = h' * dinv^2 ---------------------------
__global__ void k_selfloop() {
    int idx = blockIdx.x * blockDim.x + threadIdx.x;   // over N*16 float4s
    if (idx >= N_NODES * 16) return;
    int i = idx >> 4;
    float c = g_dinv[i]; c *= c;
    float4 v = ((const float4*)g_h)[idx];
    v.x *= c; v.y *= c; v.z *= c; v.w *= c;
    ((float4*)g_agg)[idx] = v;
}

// ---------------- edge scatter: agg[dst] += h'[src] * dinv[src]*dinv[dst] -----
__global__ void k_scatter(const int* __restrict__ src, const int* __restrict__ dst) {
    int idx = blockIdx.x * blockDim.x + threadIdx.x;   // over E*16
    if (idx >= N_EDGES * 16) return;
    int e = idx >> 4;
    int q = idx & 15;
    int s = src[e];
    int d = dst[e];
    float c = g_dinv[s] * g_dinv[d];
    float4 v = ((const float4*)g_h)[s * 16 + q];
    v.x *= c; v.y *= c; v.z *= c; v.w *= c;
    atomicAdd(((float4*)g_agg) + ((size_t)d * 16 + q), v);
}

// ---------------- bias + relu (in place on g_agg) ------------------------------
__global__ void k_bias_relu(const float* __restrict__ b) {
    size_t idx = (size_t)blockIdx.x * blockDim.x + threadIdx.x;   // over N*64
    if (idx >= (size_t)N_NODES * 64) return;
    int f = (int)(idx & 63);
    g_agg[idx] = fmaxf(g_agg[idx] + b[f], 0.f);
}

// ---------------- attention + pooling + final linear ---------------------------
// 1 warp per graph, 4 warps per block.
__global__ void k_attn(const float* __restrict__ Wa, const float* __restrict__ v,
                       const float* __restrict__ Wl, const float* __restrict__ bl,
                       float* __restrict__ out, float* __restrict__ lw) {
    __shared__ float sWa[64 * 64];
    __shared__ float sWl[128 * 32];
    __shared__ float sV[64];
    __shared__ float sBl[32];
    __shared__ float sH[4][LEADS * 64];
    __shared__ float sScore[4][LEADS];
    __shared__ float sPool[4][128];

    int tid = threadIdx.x;
    for (int i = tid; i < 4096; i += 128) { sWa[i] = Wa[i]; sWl[i] = Wl[i]; }
    if (tid < 64) sV[tid] = v[tid];
    if (tid < 32) sBl[tid] = bl[tid];
    __syncthreads();

    int w = tid >> 5, lane = tid & 31;
    int g = blockIdx.x * 4 + w;
    if (g >= NUM_GRAPHS) return;

    float* hs = sH[w];
    const float4* hg4 = (const float4*)(g_agg + (size_t)g * (LEADS * 64));
    float4* hs4 = (float4*)hs;
    #pragma unroll
    for (int j = 0; j < 6; j++) hs4[lane + 32 * j] = hg4[lane + 32 * j];
    __syncwarp();

    // energy = tanh(h @ Wa); lane owns features (lane, lane+32); k-outer loop.
    float e0[LEADS], e1[LEADS];
    #pragma unroll
    for (int l = 0; l < LEADS; l++) { e0[l] = 0.f; e1[l] = 0.f; }
    #pragma unroll 8
    for (int k = 0; k < 64; k++) {
        float w0 = sWa[k * 64 + lane];
        float w1 = sWa[k * 64 + 32 + lane];
        #pragma unroll
        for (int l = 0; l < LEADS; l++) {
            float a = hs[l * 64 + k];              // warp-broadcast
            e0[l] += a * w0;
            e1[l] += a * w1;
        }
    }
    float v0 = sV[lane], v1 = sV[lane + 32];
    #pragma unroll
    for (int l = 0; l < LEADS; l++) {
        float s = tanhf(e0[l]) * v0 + tanhf(e1[l]) * v1;
        #pragma unroll
        for (int o = 16; o > 0; o >>= 1) s += __shfl_xor_sync(0xffffffff, s, o);
        if (lane == 0) sScore[w][l] = s;
    }
    __syncwarp();

    // softmax over 12 leads (computed redundantly in each lane)
    float sc[LEADS];
    #pragma unroll
    for (int l = 0; l < LEADS; l++) sc[l] = sScore[w][l];
    float m = sc[0];
    #pragma unroll
    for (int l = 1; l < LEADS; l++) m = fmaxf(m, sc[l]);
    float sum = 0.f;
    #pragma unroll
    for (int l = 0; l < LEADS; l++) { sc[l] = expf(sc[l] - m); sum += sc[l]; }
    float inv = 1.f / sum;
    #pragma unroll
    for (int l = 0; l < LEADS; l++) sc[l] *= inv;
    if (lane < LEADS) lw[(size_t)g * LEADS + lane] = sc[lane];

    // weighted max / mean pool over leads
    #pragma unroll
    for (int half = 0; half < 2; half++) {
        int f = lane + 32 * half;
        float mx = -1e30f, sm = 0.f;
        #pragma unroll
        for (int l = 0; l < LEADS; l++) {
            float val = hs[l * 64 + f] * sc[l];
            mx = fmaxf(mx, val);
            sm += val;
        }
        sPool[w][f] = mx;
        sPool[w][64 + f] = sm * (1.f / 12.f);
    }
    __syncwarp();

    // out = relu(pooled @ Wl + bl); lane = output channel
    float acc = sBl[lane];
    #pragma unroll 16
    for (int f = 0; f < 128; f++) acc += sPool[w][f] * sWl[f * 32 + lane];
    out[(size_t)g * 32 + lane] = fmaxf(acc, 0.f);
}

// ---------------- launch --------------------------------------------------------
extern "C" void kernel_launch(void* const* d_in, const int* in_sizes, int n_in,
                              void* d_out, int out_size) {
    const float* x    = (const float*)d_in[0];
    const int*   ei   = (const int*)d_in[1];
    const int*   srcp = ei;
    const int*   dstp = ei + N_EDGES;
    // d_in[2] = batch (unused: leads are 12 consecutive nodes per graph)
    const float* W1 = (const float*)d_in[3];
    const float* b1 = (const float*)d_in[4];
    const float* W2 = (const float*)d_in[5];
    const float* b2 = (const float*)d_in[6];
    const float* W3 = (const float*)d_in[7];
    const float* b3 = (const float*)d_in[8];
    const float* Wa = (const float*)d_in[9];
    const float* vv = (const float*)d_in[10];
    const float* Wl = (const float*)d_in[11];
    const float* bl = (const float*)d_in[12];

    float* out = (float*)d_out;                        // [G,32]
    float* lw  = (float*)d_out + (size_t)NUM_GRAPHS * OUT_DIM;  // [G,12]

    float* hp;   cudaGetSymbolAddress((void**)&hp,  g_h);
    float* aggp; cudaGetSymbolAddress((void**)&aggp, g_agg);

    const int T = 256;
    // normalization
    k_deg_init<<<(N_NODES + T - 1) / T, T>>>();
    k_deg_count<<<(N_EDGES + T - 1) / T, T>>>(dstp);
    k_dinv<<<(N_NODES + T - 1) / T, T>>>();

    const int gN16 = (N_NODES * 16 + T - 1) / T;
    const int gE16 = (N_EDGES * 16 + T - 1) / T;
    const int gN64 = (int)(((size_t)N_NODES * 64 + T - 1) / T);

    // ---- layer 1: x[N,128] @ W1 ----
    k_gemm64<128, 32, 2><<<N_NODES / 32, T>>>(x, W1, hp);
    k_selfloop<<<gN16, T>>>();
    k_scatter<<<gE16, T>>>(srcp, dstp);
    k_bias_relu<<<gN64, T>>>(b1);

    // ---- layer 2 ----
    k_gemm64<64, 64, 4><<<N_NODES / 64, T>>>(aggp, W2, hp);
    k_selfloop<<<gN16, T>>>();
    k_scatter<<<gE16, T>>>(srcp, dstp);
    k_bias_relu<<<gN64, T>>>(b2);

    // ---- layer 3 ----
    k_gemm64<64, 64, 4><<<N_NODES / 64, T>>>(aggp, W3, hp);
    k_selfloop<<<gN16, T>>>();
    k_scatter<<<gE16, T>>>(srcp, dstp);
    k_bias_relu<<<gN64, T>>>(b3);

    // ---- attention + pooling + classifier ----
    k_attn<<<(NUM_GRAPHS + 3) / 4, 128>>>(Wa, vv, Wl, bl, out, lw);
}

// round 2
// speedup vs baseline: 1.1780x; 1.1780x over previous
#include <cuda_runtime.h>
#include <cuda_bf16.h>

#define N_NODES 600000
#define N_EDGES 2400000
#define LEADS 12
#define NUM_GRAPHS 50000
#define F_IN 128
#define HDIM 64
#define OUT_DIM 32

#define SCAN_NB 586   // ceil(600000/1024)

// ---------------- scratch (device globals) ------------------------------------
__device__ float g_h[(size_t)N_NODES * HDIM];    // GEMM output (pre-scaled by dinv[row])
__device__ float g_agg[(size_t)N_NODES * HDIM];  // aggregated layer output (pre-bias/relu)
__device__ float g_dinv[N_NODES];
__device__ int   g_deg[N_NODES];
__device__ int   g_rowoff[N_NODES + 1];
__device__ int   g_cursor[N_NODES];
__device__ int   g_csr[N_EDGES];
__device__ int   g_bsum[SCAN_NB];
__device__ int   g_boff[SCAN_NB];

// ---------------- degree / CSR build -------------------------------------------
__global__ void k_deg_zero() {
    int i = blockIdx.x * blockDim.x + threadIdx.x;
    if (i < N_NODES) g_deg[i] = 0;
}

__global__ void k_deg_count(const int* __restrict__ dst) {
    int e = blockIdx.x * blockDim.x + threadIdx.x;
    if (e < N_EDGES) atomicAdd(&g_deg[dst[e]], 1);
}

__global__ void k_dinv() {
    int i = blockIdx.x * blockDim.x + threadIdx.x;
    if (i < N_NODES) g_dinv[i] = rsqrtf((float)(g_deg[i] + 1));
}

// block-level inclusive scan of degrees -> exclusive row offsets + block sums
__global__ void k_scan1() {
    __shared__ int sh[1024];
    int i = blockIdx.x * 1024 + threadIdx.x;
    int v = (i < N_NODES) ? g_deg[i] : 0;
    sh[threadIdx.x] = v;
    __syncthreads();
    #pragma unroll
    for (int off = 1; off < 1024; off <<= 1) {
        int t = 0;
        if (threadIdx.x >= off) t = sh[threadIdx.x - off];
        __syncthreads();
        if (threadIdx.x >= off) sh[threadIdx.x] += t;
        __syncthreads();
    }
    if (i <= N_NODES) { /* nothing */ }
    if (i < N_NODES) g_rowoff[i] = sh[threadIdx.x] - v;   // exclusive
    if (threadIdx.x == 1023) g_bsum[blockIdx.x] = sh[1023];
}

__global__ void k_scan2() {   // single block: scan block sums
    __shared__ int sh[1024];
    int v = (threadIdx.x < SCAN_NB) ? g_bsum[threadIdx.x] : 0;
    sh[threadIdx.x] = v;
    __syncthreads();
    #pragma unroll
    for (int off = 1; off < 1024; off <<= 1) {
        int t = 0;
        if (threadIdx.x >= off) t = sh[threadIdx.x - off];
        __syncthreads();
        if (threadIdx.x >= off) sh[threadIdx.x] += t;
        __syncthreads();
    }
    if (threadIdx.x < SCAN_NB) g_boff[threadIdx.x] = sh[threadIdx.x] - v;  // exclusive
}

__global__ void k_scan3() {
    int i = blockIdx.x * blockDim.x + threadIdx.x;
    if (i < N_NODES) {
        int ro = g_rowoff[i] + g_boff[i >> 10];
        g_rowoff[i] = ro;
        g_cursor[i] = ro;
    }
    if (i == 0) g_rowoff[N_NODES] = N_EDGES;
}

__global__ void k_place(const int* __restrict__ src, const int* __restrict__ dst) {
    int e = blockIdx.x * blockDim.x + threadIdx.x;
    if (e < N_EDGES) {
        int pos = atomicAdd(&g_cursor[dst[e]], 1);
        g_csr[pos] = src[e];
    }
}

// ---------------- GEMM: C[N,64] = (act(A)[N,K] @ W[K,64]) * dinv[row] ----------
// BM=128 rows/block, 256 threads, thread tile 8 rows x 4 cols, float4 k-loads.
template<int K, bool ACT>
__global__ void k_gemm(const float* __restrict__ A, const float* __restrict__ W,
                       const float* __restrict__ bias, float* __restrict__ C) {
    constexpr int BM = 128;
    constexpr int KQ = K / 4;
    constexpr int KP = K + 4;   // padded W rows (bank-conflict free)
    extern __shared__ float smem[];
    float* sA  = smem;            // [BM][K]
    float* sWt = smem + BM * K;   // [64][K+4]  (transposed W)

    const int tid = threadIdx.x;
    const int r0 = blockIdx.x * BM;

    // W transposed into smem
    for (int i = tid; i < K * 64; i += 256) {
        int k = i >> 6, c = i & 63;
        sWt[c * KP + k] = W[i];
    }
    // A (with optional fused bias+relu) into smem
    const float4* A4 = (const float4*)A;
    const float4* B4 = (const float4*)bias;
    float4* sA4 = (float4*)sA;
    for (int i = tid; i < BM * KQ; i += 256) {
        int row = i / KQ, kq = i - row * KQ;
        float4 a = make_float4(0.f, 0.f, 0.f, 0.f);
        if (r0 + row < N_NODES) a = A4[(size_t)(r0 + row) * KQ + kq];
        if (ACT) {
            float4 b = B4[kq];
            a.x = fmaxf(a.x + b.x, 0.f);
            a.y = fmaxf(a.y + b.y, 0.f);
            a.z = fmaxf(a.z + b.z, 0.f);
            a.w = fmaxf(a.w + b.w, 0.f);
        }
        sA4[i] = a;
    }
    __syncthreads();

    const int ci = tid & 15;   // cols [4ci, 4ci+3]
    const int ri = tid >> 4;   // rows [8ri, 8ri+7]
    float acc[8][4];
    #pragma unroll
    for (int j = 0; j < 8; j++)
        #pragma unroll
        for (int c = 0; c < 4; c++) acc[j][c] = 0.f;

    const float* wbase = sWt + ci * 4 * KP;
    const float* abase = sA + ri * 8 * K;

    #pragma unroll 4
    for (int k4 = 0; k4 < KQ; k4++) {
        float4 w0 = *(const float4*)(wbase + 0 * KP + k4 * 4);
        float4 w1 = *(const float4*)(wbase + 1 * KP + k4 * 4);
        float4 w2 = *(const float4*)(wbase + 2 * KP + k4 * 4);
        float4 w3 = *(const float4*)(wbase + 3 * KP + k4 * 4);
        #pragma unroll
        for (int j = 0; j < 8; j++) {
            float4 a = *(const float4*)(abase + j * K + k4 * 4);
            acc[j][0] += a.x * w0.x; acc[j][0] += a.y * w0.y; acc[j][0] += a.z * w0.z; acc[j][0] += a.w * w0.w;
            acc[j][1] += a.x * w1.x; acc[j][1] += a.y * w1.y; acc[j][1] += a.z * w1.z; acc[j][1] += a.w * w1.w;
            acc[j][2] += a.x * w2.x; acc[j][2] += a.y * w2.y; acc[j][2] += a.z * w2.z; acc[j][2] += a.w * w2.w;
            acc[j][3] += a.x * w3.x; acc[j][3] += a.y * w3.y; acc[j][3] += a.z * w3.z; acc[j][3] += a.w * w3.w;
        }
    }

    float4* C4 = (float4*)C;
    #pragma unroll
    for (int j = 0; j < 8; j++) {
        int r = r0 + ri * 8 + j;
        if (r < N_NODES) {
            float dv = g_dinv[r];
            C4[(size_t)r * 16 + ci] = make_float4(acc[j][0] * dv, acc[j][1] * dv,
                                                  acc[j][2] * dv, acc[j][3] * dv);
        }
    }
}

// ---------------- CSR aggregation: agg[d] = dinv[d]*(h[d] + sum h[src]) --------
__global__ void k_aggregate() {
    int idx = blockIdx.x * blockDim.x + threadIdx.x;   // over N*16 float4 slots
    if (idx >= N_NODES * 16) return;
    int node = idx >> 4;
    int q = idx & 15;
    const float4* h4 = (const float4*)g_h;
    float4 acc = h4[(size_t)node * 16 + q];
    int e0 = g_rowoff[node], e1 = g_rowoff[node + 1];
    for (int e = e0; e < e1; e++) {
        int s = g_csr[e];                 // warp-uniform across the 16 q-threads
        float4 v = h4[(size_t)s * 16 + q];
        acc.x += v.x; acc.y += v.y; acc.z += v.z; acc.w += v.w;
    }
    float d = g_dinv[node];
    acc.x *= d; acc.y *= d; acc.z *= d; acc.w *= d;
    ((float4*)g_agg)[idx] = acc;
}

// ---------------- attention + pooling + final linear ---------------------------
// 1 warp per graph, 4 warps per block. Applies relu(h + b3) on load.
__global__ void k_attn(const float* __restrict__ Wa, const float* __restrict__ v,
                       const float* __restrict__ Wl, const float* __restrict__ bl,
                       const float* __restrict__ b3,
                       float* __restrict__ out, float* __restrict__ lw) {
    __shared__ float sWa[64 * 64];
    __shared__ float sWl[128 * 32];
    __shared__ float sV[64];
    __shared__ float sBl[32];
    __shared__ float sB3[64];
    __shared__ float sH[4][LEADS * 64];
    __shared__ float sScore[4][LEADS];
    __shared__ float sPool[4][128];

    int tid = threadIdx.x;
    for (int i = tid; i < 4096; i += 128) { sWa[i] = Wa[i]; sWl[i] = Wl[i]; }
    if (tid < 64) { sV[tid] = v[tid]; sB3[tid] = b3[tid]; }
    if (tid < 32) sBl[tid] = bl[tid];
    __syncthreads();

    int w = tid >> 5, lane = tid & 31;
    int g = blockIdx.x * 4 + w;
    if (g >= NUM_GRAPHS) return;

    float* hs = sH[w];
    const float4* hg4 = (const float4*)(g_agg + (size_t)g * (LEADS * 64));
    const float4* b34 = (const float4*)sB3;
    float4* hs4 = (float4*)hs;
    #pragma unroll
    for (int j = 0; j < 6; j++) {
        int id = lane + 32 * j;
        float4 hv = hg4[id];
        float4 b = b34[id & 15];
        hv.x = fmaxf(hv.x + b.x, 0.f);
        hv.y = fmaxf(hv.y + b.y, 0.f);
        hv.z = fmaxf(hv.z + b.z, 0.f);
        hv.w = fmaxf(hv.w + b.w, 0.f);
        hs4[id] = hv;
    }
    __syncwarp();

    // energy = tanh(h @ Wa); lane owns features (lane, lane+32)
    float e0[LEADS], e1[LEADS];
    #pragma unroll
    for (int l = 0; l < LEADS; l++) { e0[l] = 0.f; e1[l] = 0.f; }
    #pragma unroll 8
    for (int k = 0; k < 64; k++) {
        float w0 = sWa[k * 64 + lane];
        float w1 = sWa[k * 64 + 32 + lane];
        #pragma unroll
        for (int l = 0; l < LEADS; l++) {
            float a = hs[l * 64 + k];
            e0[l] += a * w0;
            e1[l] += a * w1;
        }
    }
    float v0 = sV[lane], v1 = sV[lane + 32];
    #pragma unroll
    for (int l = 0; l < LEADS; l++) {
        float s = tanhf(e0[l]) * v0 + tanhf(e1[l]) * v1;
        #pragma unroll
        for (int o = 16; o > 0; o >>= 1) s += __shfl_xor_sync(0xffffffff, s, o);
        if (lane == 0) sScore[w][l] = s;
    }
    __syncwarp();

    float sc[LEADS];
    #pragma unroll
    for (int l = 0; l < LEADS; l++) sc[l] = sScore[w][l];
    float m = sc[0];
    #pragma unroll
    for (int l = 1; l < LEADS; l++) m = fmaxf(m, sc[l]);
    float sum = 0.f;
    #pragma unroll
    for (int l = 0; l < LEADS; l++) { sc[l] = expf(sc[l] - m); sum += sc[l]; }
    float inv = 1.f / sum;
    #pragma unroll
    for (int l = 0; l < LEADS; l++) sc[l] *= inv;
    if (lane < LEADS) lw[(size_t)g * LEADS + lane] = sc[lane];

    #pragma unroll
    for (int half = 0; half < 2; half++) {
        int f = lane + 32 * half;
        float mx = -1e30f, sm = 0.f;
        #pragma unroll
        for (int l = 0; l < LEADS; l++) {
            float val = hs[l * 64 + f] * sc[l];
            mx = fmaxf(mx, val);
            sm += val;
        }
        sPool[w][f] = mx;
        sPool[w][64 + f] = sm * (1.f / 12.f);
    }
    __syncwarp();

    float acc = sBl[lane];
    #pragma unroll 16
    for (int f = 0; f < 128; f++) acc += sPool[w][f] * sWl[f * 32 + lane];
    out[(size_t)g * 32 + lane] = fmaxf(acc, 0.f);
}

// ---------------- launch --------------------------------------------------------
extern "C" void kernel_launch(void* const* d_in, const int* in_sizes, int n_in,
                              void* d_out, int out_size) {
    const float* x    = (const float*)d_in[0];
    const int*   ei   = (const int*)d_in[1];
    const int*   srcp = ei;
    const int*   dstp = ei + N_EDGES;
    const float* W1 = (const float*)d_in[3];
    const float* b1 = (const float*)d_in[4];
    const float* W2 = (const float*)d_in[5];
    const float* b2 = (const float*)d_in[6];
    const float* W3 = (const float*)d_in[7];
    const float* b3 = (const float*)d_in[8];
    const float* Wa = (const float*)d_in[9];
    const float* vv = (const float*)d_in[10];
    const float* Wl = (const float*)d_in[11];
    const float* bl = (const float*)d_in[12];

    float* out = (float*)d_out;                                  // [G,32]
    float* lw  = (float*)d_out + (size_t)NUM_GRAPHS * OUT_DIM;   // [G,12]

    float* hp;   cudaGetSymbolAddress((void**)&hp,  g_h);
    float* aggp; cudaGetSymbolAddress((void**)&aggp, g_agg);

    // dynamic smem sizes
    const int SM1 = 128 * 128 * 4 + 64 * 132 * 4;   // K=128: 99328 B
    const int SM2 = 128 * 64 * 4 + 64 * 68 * 4;     // K=64:  50176 B
    cudaFuncSetAttribute(k_gemm<128, false>, cudaFuncAttributeMaxDynamicSharedMemorySize, SM1);
    cudaFuncSetAttribute(k_gemm<64, true>,  cudaFuncAttributeMaxDynamicSharedMemorySize, SM2);

    const int T = 256;
    const int gN = (N_NODES + T - 1) / T;
    const int gE = (N_EDGES + T - 1) / T;

    // normalization + CSR build (once per call)
    k_deg_zero<<<gN, T>>>();
    k_deg_count<<<gE, T>>>(dstp);
    k_dinv<<<gN, T>>>();
    k_scan1<<<SCAN_NB, 1024>>>();
    k_scan2<<<1, 1024>>>();
    k_scan3<<<(N_NODES + 1023) / 1024, 1024>>>();
    k_place<<<gE, T>>>(srcp, dstp);

    const int GEMM_GRID = (N_NODES + 127) / 128;     // 4688
    const int AGG_GRID  = (N_NODES * 16 + T - 1) / T;

    // layer 1
    k_gemm<128, false><<<GEMM_GRID, 256, SM1>>>(x, W1, nullptr, hp);
    k_aggregate<<<AGG_GRID, T>>>();
    // layer 2 (bias1+relu fused into A-load)
    k_gemm<64, true><<<GEMM_GRID, 256, SM2>>>(aggp, W2, b1, hp);
    k_aggregate<<<AGG_GRID, T>>>();
    // layer 3 (bias2+relu fused into A-load)
    k_gemm<64, true><<<GEMM_GRID, 256, SM2>>>(aggp, W3, b2, hp);
    k_aggregate<<<AGG_GRID, T>>>();

    // attention + pooling + classifier (bias3+relu fused into h-load)
    k_attn<<<(NUM_GRAPHS + 3) / 4, 128>>>(Wa, vv, Wl, bl, b3, out, lw);
}

// round 3
// speedup vs baseline: 1.2023x; 1.0205x over previous
#include <cuda_runtime.h>
#include <cuda_bf16.h>

#define N_NODES 600000
#define N_EDGES 2400000
#define LEADS 12
#define NUM_GRAPHS 50000
#define F_IN 128
#define HDIM 64
#define OUT_DIM 32

#define SCAN_NB 586   // ceil(600000/1024)

// ---------------- packed fp32x2 FMA (Blackwell FFMA2, 2x fp32 throughput) ------
__device__ __forceinline__ void fma2(unsigned long long& d,
                                     unsigned long long a,
                                     unsigned long long b) {
    asm("fma.rn.f32x2 %0, %1, %2, %0;" : "+l"(d) : "l"(a), "l"(b));
}
__device__ __forceinline__ float hsum2(unsigned long long d) {
    float lo = __uint_as_float((unsigned int)(d & 0xffffffffULL));
    float hi = __uint_as_float((unsigned int)(d >> 32));
    return lo + hi;
}

// ---------------- scratch (device globals) ------------------------------------
__device__ float g_h[(size_t)N_NODES * HDIM];    // GEMM output (pre-scaled by dinv[row])
__device__ float g_agg[(size_t)N_NODES * HDIM];  // aggregated layer output (pre-bias/relu)
__device__ float g_dinv[N_NODES];
__device__ int   g_deg[N_NODES];
__device__ int   g_rowoff[N_NODES + 1];
__device__ int   g_cursor[N_NODES];
__device__ int   g_csr[N_EDGES];
__device__ int   g_bsum[SCAN_NB];
__device__ int   g_boff[SCAN_NB];

// ---------------- degree / CSR build -------------------------------------------
__global__ void k_deg_zero() {
    int i = blockIdx.x * blockDim.x + threadIdx.x;
    if (i < N_NODES) g_deg[i] = 0;
}

__global__ void k_deg_count(const int* __restrict__ dst) {
    int e = blockIdx.x * blockDim.x + threadIdx.x;
    if (e < N_EDGES) atomicAdd(&g_deg[dst[e]], 1);
}

__global__ void k_dinv() {
    int i = blockIdx.x * blockDim.x + threadIdx.x;
    if (i < N_NODES) g_dinv[i] = rsqrtf((float)(g_deg[i] + 1));
}

__global__ void k_scan1() {
    __shared__ int sh[1024];
    int i = blockIdx.x * 1024 + threadIdx.x;
    int v = (i < N_NODES) ? g_deg[i] : 0;
    sh[threadIdx.x] = v;
    __syncthreads();
    #pragma unroll
    for (int off = 1; off < 1024; off <<= 1) {
        int t = 0;
        if (threadIdx.x >= off) t = sh[threadIdx.x - off];
        __syncthreads();
        if (threadIdx.x >= off) sh[threadIdx.x] += t;
        __syncthreads();
    }
    if (i < N_NODES) g_rowoff[i] = sh[threadIdx.x] - v;   // exclusive
    if (threadIdx.x == 1023) g_bsum[blockIdx.x] = sh[1023];
}

__global__ void k_scan2() {
    __shared__ int sh[1024];
    int v = (threadIdx.x < SCAN_NB) ? g_bsum[threadIdx.x] : 0;
    sh[threadIdx.x] = v;
    __syncthreads();
    #pragma unroll
    for (int off = 1; off < 1024; off <<= 1) {
        int t = 0;
        if (threadIdx.x >= off) t = sh[threadIdx.x - off];
        __syncthreads();
        if (threadIdx.x >= off) sh[threadIdx.x] += t;
        __syncthreads();
    }
    if (threadIdx.x < SCAN_NB) g_boff[threadIdx.x] = sh[threadIdx.x] - v;
}

__global__ void k_scan3() {
    int i = blockIdx.x * blockDim.x + threadIdx.x;
    if (i < N_NODES) {
        int ro = g_rowoff[i] + g_boff[i >> 10];
        g_rowoff[i] = ro;
        g_cursor[i] = ro;
    }
    if (i == 0) g_rowoff[N_NODES] = N_EDGES;
}

__global__ void k_place(const int* __restrict__ src, const int* __restrict__ dst) {
    int e = blockIdx.x * blockDim.x + threadIdx.x;
    if (e < N_EDGES) {
        int pos = atomicAdd(&g_cursor[dst[e]], 1);
        g_csr[pos] = src[e];
    }
}

// ---------------- GEMM: C[N,64] = (act(A)[N,K] @ W[K,64]) * dinv[row] ----------
// BM=128 rows/block, 256 threads, thread tile 8 rows x 4 cols.
// Inner products packed along K via fp32x2 FMA (two k-values per instruction).
template<int K, bool ACT>
__global__ void k_gemm(const float* __restrict__ A, const float* __restrict__ W,
                       const float* __restrict__ bias, float* __restrict__ C) {
    constexpr int BM = 128;
    constexpr int KQ = K / 4;
    constexpr int KP = K + 4;   // padded W rows
    extern __shared__ float smem[];
    float* sA  = smem;            // [BM][K]
    float* sWt = smem + BM * K;   // [64][K+4]  (transposed W)

    const int tid = threadIdx.x;
    const int r0 = blockIdx.x * BM;

    for (int i = tid; i < K * 64; i += 256) {
        int k = i >> 6, c = i & 63;
        sWt[c * KP + k] = W[i];
    }
    const float4* A4 = (const float4*)A;
    const float4* B4 = (const float4*)bias;
    float4* sA4 = (float4*)sA;
    for (int i = tid; i < BM * KQ; i += 256) {
        int row = i / KQ, kq = i - row * KQ;
        float4 a = make_float4(0.f, 0.f, 0.f, 0.f);
        if (r0 + row < N_NODES) a = A4[(size_t)(r0 + row) * KQ + kq];
        if (ACT) {
            float4 b = B4[kq];
            a.x = fmaxf(a.x + b.x, 0.f);
            a.y = fmaxf(a.y + b.y, 0.f);
            a.z = fmaxf(a.z + b.z, 0.f);
            a.w = fmaxf(a.w + b.w, 0.f);
        }
        sA4[i] = a;
    }
    __syncthreads();

    const int ci = tid & 15;   // cols [4ci, 4ci+3]
    const int ri = tid >> 4;   // rows [8ri, 8ri+7]
    unsigned long long acc[8][4];
    #pragma unroll
    for (int j = 0; j < 8; j++)
        #pragma unroll
        for (int c = 0; c < 4; c++) acc[j][c] = 0ULL;

    const float* wbase = sWt + ci * 4 * KP;
    const float* abase = sA + ri * 8 * K;

    #pragma unroll 4
    for (int k4 = 0; k4 < KQ; k4++) {
        ulonglong2 w0 = *(const ulonglong2*)(wbase + 0 * KP + k4 * 4);
        ulonglong2 w1 = *(const ulonglong2*)(wbase + 1 * KP + k4 * 4);
        ulonglong2 w2 = *(const ulonglong2*)(wbase + 2 * KP + k4 * 4);
        ulonglong2 w3 = *(const ulonglong2*)(wbase + 3 * KP + k4 * 4);
        #pragma unroll
        for (int j = 0; j < 8; j++) {
            ulonglong2 a = *(const ulonglong2*)(abase + j * K + k4 * 4);
            fma2(acc[j][0], a.x, w0.x); fma2(acc[j][0], a.y, w0.y);
            fma2(acc[j][1], a.x, w1.x); fma2(acc[j][1], a.y, w1.y);
            fma2(acc[j][2], a.x, w2.x); fma2(acc[j][2], a.y, w2.y);
            fma2(acc[j][3], a.x, w3.x); fma2(acc[j][3], a.y, w3.y);
        }
    }

    float4* C4 = (float4*)C;
    #pragma unroll
    for (int j = 0; j < 8; j++) {
        int r = r0 + ri * 8 + j;
        if (r < N_NODES) {
            float dv = g_dinv[r];
            C4[(size_t)r * 16 + ci] = make_float4(hsum2(acc[j][0]) * dv,
                                                  hsum2(acc[j][1]) * dv,
                                                  hsum2(acc[j][2]) * dv,
                                                  hsum2(acc[j][3]) * dv);
        }
    }
}

// ---------------- CSR aggregation: agg[d] = dinv[d]*(h[d] + sum h[src]) --------
__global__ void k_aggregate() {
    int idx = blockIdx.x * blockDim.x + threadIdx.x;   // over N*16 float4 slots
    if (idx >= N_NODES * 16) return;
    int node = idx >> 4;
    int q = idx & 15;
    const float4* h4 = (const float4*)g_h;
    float4 acc = h4[(size_t)node * 16 + q];
    int e0 = g_rowoff[node], e1 = g_rowoff[node + 1];
    for (int e = e0; e < e1; e++) {
        int s = g_csr[e];
        float4 v = h4[(size_t)s * 16 + q];
        acc.x += v.x; acc.y += v.y; acc.z += v.z; acc.w += v.w;
    }
    float d = g_dinv[node];
    acc.x *= d; acc.y *= d; acc.z *= d; acc.w *= d;
    ((float4*)g_agg)[idx] = acc;
}

// ---------------- attention + pooling + final linear ---------------------------
// 1 warp per graph, 4 warps per block. Applies relu(h + b3) on load.
// Energy GEMM uses fp32x2 FMA packed along k (Wa transposed in smem).
__global__ void k_attn(const float* __restrict__ Wa, const float* __restrict__ v,
                       const float* __restrict__ Wl, const float* __restrict__ bl,
                       const float* __restrict__ b3,
                       float* __restrict__ out, float* __restrict__ lw) {
    __shared__ float sWaT[64 * 68];    // transposed Wa: [col][k] padded
    __shared__ float sWl[128 * 32];
    __shared__ float sV[64];
    __shared__ float sBl[32];
    __shared__ float sB3[64];
    __shared__ float sH[4][LEADS * 64];
    __shared__ float sScore[4][LEADS];
    __shared__ float sPool[4][128];

    int tid = threadIdx.x;
    for (int i = tid; i < 4096; i += 128) {
        int k = i >> 6, c = i & 63;
        sWaT[c * 68 + k] = Wa[i];
        sWl[i] = Wl[i];
    }
    if (tid < 64) { sV[tid] = v[tid]; sB3[tid] = b3[tid]; }
    if (tid < 32) sBl[tid] = bl[tid];
    __syncthreads();

    int w = tid >> 5, lane = tid & 31;
    int g = blockIdx.x * 4 + w;
    if (g >= NUM_GRAPHS) return;

    float* hs = sH[w];
    const float4* hg4 = (const float4*)(g_agg + (size_t)g * (LEADS * 64));
    const float4* b34 = (const float4*)sB3;
    float4* hs4 = (float4*)hs;
    #pragma unroll
    for (int j = 0; j < 6; j++) {
        int id = lane + 32 * j;
        float4 hv = hg4[id];
        float4 b = b34[id & 15];
        hv.x = fmaxf(hv.x + b.x, 0.f);
        hv.y = fmaxf(hv.y + b.y, 0.f);
        hv.z = fmaxf(hv.z + b.z, 0.f);
        hv.w = fmaxf(hv.w + b.w, 0.f);
        hs4[id] = hv;
    }
    __syncwarp();

    // energy = tanh(h @ Wa); lane owns output cols (lane, lane+32), k packed x2
    unsigned long long e0[LEADS], e1[LEADS];
    #pragma unroll
    for (int l = 0; l < LEADS; l++) { e0[l] = 0ULL; e1[l] = 0ULL; }
    const float* w0base = sWaT + lane * 68;
    const float* w1base = sWaT + (lane + 32) * 68;
    #pragma unroll 4
    for (int k4 = 0; k4 < 16; k4++) {
        ulonglong2 w0 = *(const ulonglong2*)(w0base + k4 * 4);
        ulonglong2 w1 = *(const ulonglong2*)(w1base + k4 * 4);
        #pragma unroll
        for (int l = 0; l < LEADS; l++) {
            ulonglong2 a = *(const ulonglong2*)(hs + l * 64 + k4 * 4);
            fma2(e0[l], a.x, w0.x); fma2(e0[l], a.y, w0.y);
            fma2(e1[l], a.x, w1.x); fma2(e1[l], a.y, w1.y);
        }
    }
    float v0 = sV[lane], v1 = sV[lane + 32];
    #pragma unroll
    for (int l = 0; l < LEADS; l++) {
        float s = tanhf(hsum2(e0[l])) * v0 + tanhf(hsum2(e1[l])) * v1;
        #pragma unroll
        for (int o = 16; o > 0; o >>= 1) s += __shfl_xor_sync(0xffffffff, s, o);
        if (lane == 0) sScore[w][l] = s;
    }
    __syncwarp();

    float sc[LEADS];
    #pragma unroll
    for (int l = 0; l < LEADS; l++) sc[l] = sScore[w][l];
    float m = sc[0];
    #pragma unroll
    for (int l = 1; l < LEADS; l++) m = fmaxf(m, sc[l]);
    float sum = 0.f;
    #pragma unroll
    for (int l = 0; l < LEADS; l++) { sc[l] = expf(sc[l] - m); sum += sc[l]; }
    float inv = 1.f / sum;
    #pragma unroll
    for (int l = 0; l < LEADS; l++) sc[l] *= inv;
    if (lane < LEADS) lw[(size_t)g * LEADS + lane] = sc[lane];

    #pragma unroll
    for (int half = 0; half < 2; half++) {
        int f = lane + 32 * half;
        float mx = -1e30f, sm = 0.f;
        #pragma unroll
        for (int l = 0; l < LEADS; l++) {
            float val = hs[l * 64 + f] * sc[l];
            mx = fmaxf(mx, val);
            sm += val;
        }
        sPool[w][f] = mx;
        sPool[w][64 + f] = sm * (1.f / 12.f);
    }
    __syncwarp();

    float acc = sBl[lane];
    #pragma unroll 16
    for (int f = 0; f < 128; f++) acc += sPool[w][f] * sWl[f * 32 + lane];
    out[(size_t)g * 32 + lane] = fmaxf(acc, 0.f);
}

// ---------------- launch --------------------------------------------------------
extern "C" void kernel_launch(void* const* d_in, const int* in_sizes, int n_in,
                              void* d_out, int out_size) {
    const float* x    = (const float*)d_in[0];
    const int*   ei   = (const int*)d_in[1];
    const int*   srcp = ei;
    const int*   dstp = ei + N_EDGES;
    const float* W1 = (const float*)d_in[3];
    const float* b1 = (const float*)d_in[4];
    const float* W2 = (const float*)d_in[5];
    const float* b2 = (const float*)d_in[6];
    const float* W3 = (const float*)d_in[7];
    const float* b3 = (const float*)d_in[8];
    const float* Wa = (const float*)d_in[9];
    const float* vv = (const float*)d_in[10];
    const float* Wl = (const float*)d_in[11];
    const float* bl = (const float*)d_in[12];

    float* out = (float*)d_out;                                  // [G,32]
    float* lw  = (float*)d_out + (size_t)NUM_GRAPHS * OUT_DIM;   // [G,12]

    float* hp;   cudaGetSymbolAddress((void**)&hp,  g_h);
    float* aggp; cudaGetSymbolAddress((void**)&aggp, g_agg);

    const int SM1 = 128 * 128 * 4 + 64 * 132 * 4;   // K=128: 99328 B
    const int SM2 = 128 * 64 * 4 + 64 * 68 * 4;     // K=64:  50176 B
    cudaFuncSetAttribute(k_gemm<128, false>, cudaFuncAttributeMaxDynamicSharedMemorySize, SM1);
    cudaFuncSetAttribute(k_gemm<64, true>,  cudaFuncAttributeMaxDynamicSharedMemorySize, SM2);

    const int T = 256;
    const int gN = (N_NODES + T - 1) / T;
    const int gE = (N_EDGES + T - 1) / T;

    k_deg_zero<<<gN, T>>>();
    k_deg_count<<<gE, T>>>(dstp);
    k_dinv<<<gN, T>>>();
    k_scan1<<<SCAN_NB, 1024>>>();
    k_scan2<<<1, 1024>>>();
    k_scan3<<<(N_NODES + 1023) / 1024, 1024>>>();
    k_place<<<gE, T>>>(srcp, dstp);

    const int GEMM_GRID = (N_NODES + 127) / 128;
    const int AGG_GRID  = (N_NODES * 16 + T - 1) / T;

    k_gemm<128, false><<<GEMM_GRID, 256, SM1>>>(x, W1, nullptr, hp);
    k_aggregate<<<AGG_GRID, T>>>();
    k_gemm<64, true><<<GEMM_GRID, 256, SM2>>>(aggp, W2, b1, hp);
    k_aggregate<<<AGG_GRID, T>>>();
    k_gemm<64, true><<<GEMM_GRID, 256, SM2>>>(aggp, W3, b2, hp);
    k_aggregate<<<AGG_GRID, T>>>();

    k_attn<<<(NUM_GRAPHS + 3) / 4, 128>>>(Wa, vv, Wl, bl, b3, out, lw);
}